// round 13
// baseline (speedup 1.0000x reference)
#include <cuda_runtime.h>

#define SZ 256
#define NCH 8
#define NPIX (SZ*SZ)
#define WPR 8         // words per row

// Per-channel occupancy bitmasks: 8 channels x 256 rows x 8 words = 64KB
__device__ unsigned int g_maskbits[NCH * SZ * WPR];

__global__ __launch_bounds__(1024) void build_masks_kernel(const int* __restrict__ lookup) {
    int tid = threadIdx.x;
    int y = blockIdx.x * 4 + (tid >> 8);
    int x = tid & 255;
    int v = lookup[y * SZ + x];
    int w = x >> 5;
    #pragma unroll
    for (int c = 0; c < NCH; ++c) {
        unsigned int mk = __ballot_sync(0xFFFFFFFFu, v == c + 1);
        if ((x & 31) == 0)
            g_maskbits[(c * SZ + y) * WPR + w] = mk;
    }
}

// Top-4 insert (ascending 32-bit keys (d2<<16)|idx == top_k order: smallest d2,
// ties -> smallest flat idx).
#define INS32(key)                                                   \
    do { unsigned int _k = (key);                                    \
        if (_k < k3) {                                               \
            k3 = _k;                                                 \
            if (k3 < k2) {                                           \
                unsigned int _t = k2; k2 = k3; k3 = _t;              \
                if (k2 < k1) {                                       \
                    _t = k1; k1 = k2; k2 = _t;                       \
                    if (k1 < k0) { _t = k0; k0 = k1; k1 = _t; }      \
                }                                                    \
            }                                                        \
        }                                                            \
    } while (0)

static __device__ __forceinline__ void process_pixel(
    const unsigned int* __restrict__ m, const unsigned char* __restrict__ isq,
    const float* __restrict__ img, float* __restrict__ out,
    int c, int y0, int x0)
{
    const int pix = (y0 << 8) + x0;

    // Filled pixel keeps its (masked) value
    if ((m[(y0 << 3) + (x0 >> 5)] >> (x0 & 31)) & 1u) {
        out[c * NPIX + pix] = __ldg(&img[pix]);
        return;
    }

    unsigned int k0 = ~0u, k1 = ~0u, k2 = ~0u, k3 = ~0u;
    bool done = false;

    // ---------------- Fast path: interior pixel, seed succeeds ----------------
    // Interior: x0,y0 in [7,248]. If the 5x15 seed yields 4 neighbors, then
    // B <= 2^2+7^2 = 53, continuation dy <= 7 and half-width u <= 6, so every
    // scanned row/column is in bounds and the result is always exact (53 < 64).
    if (x0 >= 7 && x0 <= 248 && y0 >= 7 && y0 <= 248) {
        const int xlo = x0 - 7;
        const int wl  = xlo >> 5;
        const int sh  = xlo & 31;
        #pragma unroll
        for (int dy = -2; dy <= 2; ++dy) {
            const unsigned int* row = &m[((y0 + dy) << 3) + wl];
            unsigned int win = __funnelshift_r(row[0], row[1], sh) & 0x7FFFu;
            unsigned int base = ((unsigned int)(dy * dy) << 16)
                              + (unsigned int)(((y0 + dy) << 8) + xlo);
            while (win) {
                int b = __ffs(win) - 1;
                win &= win - 1;
                int dx = b - 7;
                INS32(base + (unsigned int)b + ((unsigned int)(dx * dx) << 16));
            }
        }
        if (k3 != ~0u) {
            for (int dy = 3; dy <= 7; ++dy) {
                unsigned int B = k3 >> 16;
                unsigned int dy2 = (unsigned int)(dy * dy);
                if (dy2 > B) break;
                int u = isq[B - dy2];                 // exact floor(sqrt)
                int xl = x0 - u;
                int wl2 = xl >> 5, sh2 = xl & 31;
                unsigned int wmask = (2u << (2 * u)) - 1u;   // 2u+1 bits
                #pragma unroll
                for (int s = 0; s < 2; ++s) {
                    int yy = s ? y0 + dy : y0 - dy;
                    const unsigned int* row = &m[(yy << 3) + wl2];
                    unsigned int win = __funnelshift_r(row[0], row[1], sh2) & wmask;
                    unsigned int base = (dy2 << 16)
                                      + (unsigned int)((yy << 8) + xl);
                    while (win) {
                        int b = __ffs(win) - 1;
                        win &= win - 1;
                        int dx = b - u;
                        INS32(base + (unsigned int)b +
                              ((unsigned int)(dx * dx) << 16));
                    }
                }
            }
            done = true;   // provably exact: final d2_4 <= 53 < 64
        }
    }

    unsigned int ridx[4], rd2[4];

    if (!done) {
        // -------------- General path (borders / sparse seed) --------------
        auto scan_row = [&](int yy, int lo, int hi) {
            if ((unsigned)yy >= SZ) return;
            lo = lo < 0 ? 0 : lo;
            hi = hi > SZ - 1 ? SZ - 1 : hi;
            const unsigned int* row = &m[yy << 3];
            const int wl = lo >> 5;
            unsigned int win = __funnelshift_r(row[wl], row[wl + 1], lo);
            win &= 0xFFFFFFFFu >> (31 - (hi - lo));
            if (!win) return;
            const int dy = yy - y0;
            const unsigned int base =
                ((unsigned int)(dy * dy) << 16) + (unsigned int)((yy << 8) + lo);
            const int off = lo - x0;
            do {
                int b = __ffs(win) - 1;
                win &= win - 1;
                int dx = b + off;
                INS32(base + (unsigned int)b + ((unsigned int)(dx * dx) << 16));
            } while (win);
        };

        // Seed (only if not already done by the fast path)
        if (!(x0 >= 7 && x0 <= 248 && y0 >= 7 && y0 <= 248)) {
            #pragma unroll
            for (int dy = -2; dy <= 2; ++dy)
                scan_row(y0 + dy, x0 - 7, x0 + 7);
        }

        // Continuation: width 7 until 4 held; then inclusive floor(sqrt(B-dy^2))
        for (int dy = 3; dy < SZ; ++dy) {
            int u = 7;
            if (k3 != ~0u) {
                unsigned int B = k3 >> 16;
                unsigned int dy2 = (unsigned int)(dy * dy);
                if (dy2 > B) break;
                int rem = (int)(B - dy2);
                u = __float2int_rd(sqrtf((float)rem));
                if ((u + 1) * (u + 1) <= rem) ++u;
                if (u * u > rem) --u;
                if (u > 7) u = 7;   // window width stays <= 15 bits
            }
            scan_row(y0 - dy, x0 - u, x0 + u);
            scan_row(y0 + dy, x0 - u, x0 + u);
        }

        // Skipped cells have |dx|>7 (d2>=64) or d2 > B >= final d2_4.
        // Exact iff final d2_4 < 64; else exact expanding-ring fallback.
        if (!(k3 != ~0u && (k3 >> 16) < 64u)) {
            unsigned long long b0 = ~0ULL, b1 = ~0ULL, b2 = ~0ULL, b3 = ~0ULL;
            int found = 0;
            auto visit = [&](int yy, int xx) {
                if ((unsigned)yy >= SZ || (unsigned)xx >= SZ) return;
                unsigned int word = m[(yy << 3) + (xx >> 5)];
                if ((word >> (xx & 31)) & 1u) {
                    int dy = yy - y0, dx = xx - x0;
                    unsigned int d2 = (unsigned int)(dy * dy + dx * dx);
                    unsigned long long key =
                        ((unsigned long long)d2 << 16) | (unsigned int)((yy << 8) + xx);
                    ++found;
                    if (key < b3) {
                        b3 = key;
                        if (b3 < b2) {
                            unsigned long long t = b2; b2 = b3; b3 = t;
                            if (b2 < b1) {
                                t = b1; b1 = b2; b2 = t;
                                if (b1 < b0) { t = b0; b0 = b1; b1 = t; }
                            }
                        }
                    }
                }
            };
            for (int r = 1; r < SZ; ++r) {
                if (found >= 4 && (unsigned int)(r * r) > (unsigned int)(b3 >> 16)) break;
                int yt = y0 - r, yb = y0 + r;
                for (int xx = x0 - r; xx <= x0 + r; ++xx) { visit(yt, xx); visit(yb, xx); }
                int xl = x0 - r, xr = x0 + r;
                for (int yy = y0 - r + 1; yy <= y0 + r - 1; ++yy) { visit(yy, xl); visit(yy, xr); }
            }
            unsigned long long keys[4] = { b0, b1, b2, b3 };
            #pragma unroll
            for (int i = 0; i < 4; ++i) {
                ridx[i] = (unsigned int)(keys[i] & 0xFFFFu);
                rd2[i]  = (unsigned int)(keys[i] >> 16);
            }
            goto output;
        }
    }

    ridx[0] = k0 & 0xFFFFu; rd2[0] = k0 >> 16;
    ridx[1] = k1 & 0xFFFFu; rd2[1] = k1 >> 16;
    ridx[2] = k2 & 0xFFFFu; rd2[2] = k2 >> 16;
    ridx[3] = k3 & 0xFFFFu; rd2[3] = k3 >> 16;

output:
    // Weighted by distance (as in reference), in top_k order.
    float num = 0.0f, den = 0.0f;
    #pragma unroll
    for (int i = 0; i < 4; ++i) {
        float dist = sqrtf((float)rd2[i]) * (1.0f / 256.0f);  // == sqrt(d2/65536)
        num += __ldg(&img[ridx[i]]) * dist;
        den += dist;
    }
    out[c * NPIX + pix] = num / den;
}

__global__ __launch_bounds__(512, 4) void knn_fill_kernel(
    const float* __restrict__ img, float* __restrict__ out)
{
    const int c   = blockIdx.y;          // channel 0..7
    const int tid = threadIdx.x;         // 0..511
    const int x0  = tid & 255;           // col
    const int sub = tid >> 8;            // which of the 2 rows

    // Channel bitmask (8KB) + 4 pad words for the wl=7 speculative read
    // (pad bits are always masked out of the window, value irrelevant).
    __shared__ __align__(16) unsigned int m[SZ * WPR + 4];
    __shared__ unsigned char isq[128];   // floor(sqrt(r)) for r in [0,127]
    if (tid < 256) {
        const uint4* src = (const uint4*)&g_maskbits[c * SZ * WPR];
        uint4* dst = (uint4*)m;
        dst[tid]       = src[tid];
        dst[tid + 256] = src[tid + 256];
    } else if (tid < 384) {
        int r = tid - 256;
        int u = __float2int_rd(sqrtf((float)r));
        if ((u + 1) * (u + 1) <= r) ++u;
        if (u * u > r) --u;
        isq[r] = (unsigned char)u;
    }
    __syncthreads();

    // Two rows per block, processed by independent warps.
    process_pixel(m, isq, img, out, c, blockIdx.x * 2 + sub, x0);
}

extern "C" void kernel_launch(void* const* d_in, const int* in_sizes, int n_in,
                              void* d_out, int out_size) {
    const float* coded  = (const float*)d_in[0];   // [1,1,256,256]
    const int*   lookup = (const int*)d_in[1];     // [256,256]
    float* out = (float*)d_out;                    // [1,8,256,256]

    build_masks_kernel<<<SZ / 4, 1024>>>(lookup);
    dim3 grid(SZ / 2, NCH);
    knn_fill_kernel<<<grid, 512>>>(coded, out);
}

// round 15
// speedup vs baseline: 1.2094x; 1.2094x over previous
#include <cuda_runtime.h>

#define SZ 256
#define NCH 8
#define NPIX (SZ*SZ)
#define WPR 8         // words per row

// Per-channel occupancy bitmasks: 8 channels x 256 rows x 8 words = 64KB
__device__ unsigned int g_maskbits[NCH * SZ * WPR];

__global__ __launch_bounds__(1024) void build_masks_kernel(const int* __restrict__ lookup) {
    int tid = threadIdx.x;
    int y = blockIdx.x * 4 + (tid >> 8);
    int x = tid & 255;
    int v = lookup[y * SZ + x];
    int w = x >> 5;
    #pragma unroll
    for (int c = 0; c < NCH; ++c) {
        unsigned int mk = __ballot_sync(0xFFFFFFFFu, v == c + 1);
        if ((x & 31) == 0)
            g_maskbits[(c * SZ + y) * WPR + w] = mk;
    }
}

// Top-4 insert (ascending 32-bit keys (d2<<16)|idx == top_k order: smallest d2,
// ties -> smallest flat idx).
#define INS32(key)                                                   \
    do { unsigned int _k = (key);                                    \
        if (_k < k3) {                                               \
            k3 = _k;                                                 \
            if (k3 < k2) {                                           \
                unsigned int _t = k2; k2 = k3; k3 = _t;              \
                if (k2 < k1) {                                       \
                    _t = k1; k1 = k2; k2 = _t;                       \
                    if (k1 < k0) { _t = k0; k0 = k1; k1 = _t; }      \
                }                                                    \
            }                                                        \
        }                                                            \
    } while (0)

static __device__ __forceinline__ void process_pixel(
    const unsigned int* __restrict__ m, const unsigned char* __restrict__ isq,
    const float* __restrict__ sqlut, const float* __restrict__ img,
    float* __restrict__ out, int c, int y0, int x0)
{
    const int pix = (y0 << 8) + x0;

    // Filled pixel keeps its (masked) value
    if ((m[(y0 << 3) + (x0 >> 5)] >> (x0 & 31)) & 1u) {
        out[c * NPIX + pix] = __ldg(&img[pix]);
        return;
    }

    unsigned int k0 = ~0u, k1 = ~0u, k2 = ~0u, k3 = ~0u;
    bool done = false;

    // ---------------- Fast path: interior pixel, seed succeeds ----------------
    // Interior: x0,y0 in [7,248]. If the 5x15 seed yields 4 neighbors, then
    // B <= 2^2+7^2 = 53, continuation dy <= 7 and half-width u <= 6, so every
    // scanned row is in bounds and the result is always exact (53 < 256).
    if (x0 >= 7 && x0 <= 248 && y0 >= 7 && y0 <= 248) {
        const int xlo = x0 - 7;
        const int wl  = xlo >> 5;
        const int sh  = xlo & 31;
        const unsigned int* row = &m[((y0 - 2) << 3) + wl];
        #pragma unroll
        for (int dy = -2; dy <= 2; ++dy, row += WPR) {
            unsigned int win = __funnelshift_r(row[0], row[1], sh) & 0x7FFFu;
            unsigned int base = ((unsigned int)(dy * dy) << 16)
                              + (unsigned int)(((y0 + dy) << 8) + xlo);
            while (win) {
                int b = __ffs(win) - 1;
                win &= win - 1;
                int dx = b - 7;
                INS32(base + (unsigned int)b + ((unsigned int)(dx * dx) << 16));
            }
        }
        if (k3 != ~0u) {
            for (int dy = 3; dy <= 7; ++dy) {
                unsigned int B = k3 >> 16;
                unsigned int dy2 = (unsigned int)(dy * dy);
                if (dy2 > B) break;
                int u = isq[B - dy2];                 // exact floor(sqrt), <= 6
                int xl = x0 - u;
                int wl2 = xl >> 5, sh2 = xl & 31;
                unsigned int wmask = (2u << (2 * u)) - 1u;   // 2u+1 bits
                #pragma unroll
                for (int s = 0; s < 2; ++s) {
                    int yy = s ? y0 + dy : y0 - dy;
                    const unsigned int* r2 = &m[(yy << 3) + wl2];
                    unsigned int win = __funnelshift_r(r2[0], r2[1], sh2) & wmask;
                    unsigned int base = (dy2 << 16)
                                      + (unsigned int)((yy << 8) + xl);
                    while (win) {
                        int b = __ffs(win) - 1;
                        win &= win - 1;
                        int dx = b - u;
                        INS32(base + (unsigned int)b +
                              ((unsigned int)(dx * dx) << 16));
                    }
                }
            }
            done = true;   // provably exact: final d2_4 <= 53
        }
    }

    unsigned int ridx[4], rd2[4];

    if (!done) {
        // RESET: the failed fast-path seed may have left partial candidates in
        // k0..k3; the general loop rescans those rows at full width, and stale
        // entries would be re-inserted as duplicates (strict-< insert would
        // then hold the same neighbor twice). Start clean.
        k0 = k1 = k2 = k3 = ~0u;

        // ------- General path (borders / sparse seed): width-15 windows -------
        // Rows in increasing |dy|; width 15 until 4 held, then inclusive
        // floor(sqrt(B - dy^2)) (capped at 15). Every skipped cell has either
        // |dx| > 15 (d2 >= 256) or d2 > B >= final d2_4 -> exact iff final
        // d2_4 < 256. Max inserted d2 = 255^2 + 15^2 = 65250 < 2^16, so 32-bit
        // keys stay valid and below the ~0u sentinel.
        auto scan_row = [&](int yy, int lo, int hi) {
            if ((unsigned)yy >= SZ) return;
            lo = lo < 0 ? 0 : lo;
            hi = hi > SZ - 1 ? SZ - 1 : hi;
            const unsigned int* row = &m[yy << 3];
            const int wl = lo >> 5;
            // row[wl+1] may read the next row's word 0 (or the pad on the last
            // row); those bits are always masked out of the window.
            unsigned int win = __funnelshift_r(row[wl], row[wl + 1], lo);
            win &= 0xFFFFFFFFu >> (31 - (hi - lo));
            if (!win) return;
            const int dy = yy - y0;
            const unsigned int base =
                ((unsigned int)(dy * dy) << 16) + (unsigned int)((yy << 8) + lo);
            const int off = lo - x0;
            do {
                int b = __ffs(win) - 1;
                win &= win - 1;
                int dx = b + off;
                INS32(base + (unsigned int)b + ((unsigned int)(dx * dx) << 16));
            } while (win);
        };

        for (int dy = 0; dy < SZ; ++dy) {
            int u = 15;
            if (k3 != ~0u) {
                unsigned int B = k3 >> 16;
                unsigned int dy2 = (unsigned int)(dy * dy);
                if (dy2 > B) break;
                unsigned int rem = B - dy2;
                u = (rem >= 225u) ? 15 : (int)isq[rem];  // exact floor(sqrt)<=15
            }
            scan_row(y0 - dy, x0 - u, x0 + u);
            if (dy > 0) scan_row(y0 + dy, x0 - u, x0 + u);
        }

        if (!(k3 != ~0u && (k3 >> 16) < 256u)) {
            // ---- Essentially unreachable exact fallback: expanding rings ----
            unsigned long long b0 = ~0ULL, b1 = ~0ULL, b2 = ~0ULL, b3 = ~0ULL;
            int found = 0;
            auto visit = [&](int yy, int xx) {
                if ((unsigned)yy >= SZ || (unsigned)xx >= SZ) return;
                unsigned int word = m[(yy << 3) + (xx >> 5)];
                if ((word >> (xx & 31)) & 1u) {
                    int dy = yy - y0, dx = xx - x0;
                    unsigned int d2 = (unsigned int)(dy * dy + dx * dx);
                    unsigned long long key =
                        ((unsigned long long)d2 << 16) | (unsigned int)((yy << 8) + xx);
                    ++found;
                    if (key < b3) {
                        b3 = key;
                        if (b3 < b2) {
                            unsigned long long t = b2; b2 = b3; b3 = t;
                            if (b2 < b1) {
                                t = b1; b1 = b2; b2 = t;
                                if (b1 < b0) { t = b0; b0 = b1; b1 = t; }
                            }
                        }
                    }
                }
            };
            for (int r = 1; r < SZ; ++r) {
                if (found >= 4 && (unsigned int)(r * r) > (unsigned int)(b3 >> 16)) break;
                int yt = y0 - r, yb = y0 + r;
                for (int xx = x0 - r; xx <= x0 + r; ++xx) { visit(yt, xx); visit(yb, xx); }
                int xl = x0 - r, xr = x0 + r;
                for (int yy = y0 - r + 1; yy <= y0 + r - 1; ++yy) { visit(yy, xl); visit(yy, xr); }
            }
            unsigned long long keys[4] = { b0, b1, b2, b3 };
            #pragma unroll
            for (int i = 0; i < 4; ++i) {
                ridx[i] = (unsigned int)(keys[i] & 0xFFFFu);
                rd2[i]  = (unsigned int)(keys[i] >> 16);
            }
            goto output;
        }
    }

    ridx[0] = k0 & 0xFFFFu; rd2[0] = k0 >> 16;
    ridx[1] = k1 & 0xFFFFu; rd2[1] = k1 >> 16;
    ridx[2] = k2 & 0xFFFFu; rd2[2] = k2 >> 16;
    ridx[3] = k3 & 0xFFFFu; rd2[3] = k3 >> 16;

output:
    // Weighted by distance (as in reference), in top_k order. sqlut[d2] is
    // computed with the identical expression -> bit-exact; d2 < 256 on every
    // gated path, runtime check only matters for the fallback.
    float num = 0.0f, den = 0.0f;
    #pragma unroll
    for (int i = 0; i < 4; ++i) {
        unsigned int d2 = rd2[i];
        float dist = (d2 < 256u) ? sqlut[d2]
                                 : sqrtf((float)d2) * (1.0f / 256.0f);
        num += __ldg(&img[ridx[i]]) * dist;
        den += dist;
    }
    out[c * NPIX + pix] = num / den;
}

__global__ __launch_bounds__(512, 4) void knn_fill_kernel(
    const float* __restrict__ img, float* __restrict__ out)
{
    const int c   = blockIdx.y;          // channel 0..7
    const int tid = threadIdx.x;         // 0..511
    const int x0  = tid & 255;           // col
    const int sub = tid >> 8;            // which of the 2 rows

    // Channel bitmask (8KB) + 4 pad words for the last-row speculative read
    // (pad bits are always masked out of the window, value irrelevant).
    __shared__ __align__(16) unsigned int m[SZ * WPR + 4];
    __shared__ unsigned char isq[256];   // floor(sqrt(r)), r in [0,255]
    __shared__ float sqlut[256];         // sqrtf(r)/256, r in [0,255]
    if (tid < 256) {
        const uint4* src = (const uint4*)&g_maskbits[c * SZ * WPR];
        uint4* dst = (uint4*)m;
        dst[tid]       = src[tid];
        dst[tid + 256] = src[tid + 256];
    } else {
        int r = tid - 256;               // 0..255
        int u = __float2int_rd(sqrtf((float)r));
        if ((u + 1) * (u + 1) <= r) ++u;
        if (u * u > r) --u;
        isq[r] = (unsigned char)u;
        sqlut[r] = sqrtf((float)r) * (1.0f / 256.0f);
    }
    __syncthreads();

    // Two rows per block, processed by independent warps.
    process_pixel(m, isq, sqlut, img, out, c, blockIdx.x * 2 + sub, x0);
}

extern "C" void kernel_launch(void* const* d_in, const int* in_sizes, int n_in,
                              void* d_out, int out_size) {
    const float* coded  = (const float*)d_in[0];   // [1,1,256,256]
    const int*   lookup = (const int*)d_in[1];     // [256,256]
    float* out = (float*)d_out;                    // [1,8,256,256]

    build_masks_kernel<<<SZ / 4, 1024>>>(lookup);
    dim3 grid(SZ / 2, NCH);
    knn_fill_kernel<<<grid, 512>>>(coded, out);
}

// round 16
// speedup vs baseline: 1.3944x; 1.1530x over previous
#include <cuda_runtime.h>

#define SZ 256
#define NCH 8
#define NPIX (SZ*SZ)
#define WPR 8         // words per row

// Per-channel occupancy bitmasks: 8 channels x 256 rows x 8 words = 64KB
__device__ unsigned int g_maskbits[NCH * SZ * WPR];

__global__ __launch_bounds__(1024) void build_masks_kernel(const int* __restrict__ lookup) {
    int tid = threadIdx.x;
    int y = blockIdx.x * 4 + (tid >> 8);
    int x = tid & 255;
    int v = lookup[y * SZ + x];
    int w = x >> 5;
    #pragma unroll
    for (int c = 0; c < NCH; ++c) {
        unsigned int mk = __ballot_sync(0xFFFFFFFFu, v == c + 1);
        if ((x & 31) == 0)
            g_maskbits[(c * SZ + y) * WPR + w] = mk;
    }
#if defined(CUDA_VERSION) || __CUDA_ARCH__ >= 900
    cudaTriggerProgrammaticLaunchCompletion();
#endif
}

// Branchless top-4 insert (ascending 32-bit keys (d2<<16)|idx == top_k order:
// smallest d2, ties -> smallest flat idx). Insertion network: 7 IMNMX, no
// branches/predication-depth divergence. Maintains k0<=k1<=k2<=k3.
#define INS32(key)                                                    \
    do { unsigned int _x = (key);                                     \
        unsigned int _y  = umin(_x, k3);                              \
        k3 = umax(k2, _y); unsigned int _y2 = umin(k2, _y);           \
        k2 = umax(k1, _y2); unsigned int _y1 = umin(k1, _y2);         \
        k1 = umax(k0, _y1); k0 = umin(k0, _y1);                       \
    } while (0)

static __device__ __forceinline__ void process_pixel(
    const unsigned int* __restrict__ m, const unsigned char* __restrict__ isq,
    const float* __restrict__ sqlut, const float* __restrict__ img,
    float* __restrict__ out, int c, int y0, int x0)
{
    const int pix = (y0 << 8) + x0;

    // Filled pixel keeps its (masked) value
    if ((m[(y0 << 3) + (x0 >> 5)] >> (x0 & 31)) & 1u) {
        out[c * NPIX + pix] = __ldg(&img[pix]);
        return;
    }

    unsigned int k0 = ~0u, k1 = ~0u, k2 = ~0u, k3 = ~0u;
    bool done = false;

    // ---------------- Fast path: interior pixel, seed succeeds ----------------
    // Interior: x0,y0 in [7,248]. If the 5x15 seed yields 4 neighbors, then
    // B <= 2^2+7^2 = 53, continuation dy <= 7 and half-width u <= 6, so every
    // scanned row is in bounds and the result is always exact (53 < 256).
    if (x0 >= 7 && x0 <= 248 && y0 >= 7 && y0 <= 248) {
        const int xlo = x0 - 7;
        const int wl  = xlo >> 5;
        const int sh  = xlo & 31;
        const unsigned int* row = &m[((y0 - 2) << 3) + wl];
        #pragma unroll
        for (int dy = -2; dy <= 2; ++dy, row += WPR) {
            unsigned int win = __funnelshift_r(row[0], row[1], sh) & 0x7FFFu;
            unsigned int base = ((unsigned int)(dy * dy) << 16)
                              + (unsigned int)(((y0 + dy) << 8) + xlo);
            while (win) {
                int b = __ffs(win) - 1;
                win &= win - 1;
                int dx = b - 7;
                INS32(base + (unsigned int)b + ((unsigned int)(dx * dx) << 16));
            }
        }
        if (k3 != ~0u) {
            for (int dy = 3; dy <= 7; ++dy) {
                unsigned int B = k3 >> 16;
                unsigned int dy2 = (unsigned int)(dy * dy);
                if (dy2 > B) break;
                int u = isq[B - dy2];                 // exact floor(sqrt), <= 6
                int xl = x0 - u;
                int wl2 = xl >> 5, sh2 = xl & 31;
                unsigned int wmask = (2u << (2 * u)) - 1u;   // 2u+1 bits
                #pragma unroll
                for (int s = 0; s < 2; ++s) {
                    int yy = s ? y0 + dy : y0 - dy;
                    const unsigned int* r2 = &m[(yy << 3) + wl2];
                    unsigned int win = __funnelshift_r(r2[0], r2[1], sh2) & wmask;
                    unsigned int base = (dy2 << 16)
                                      + (unsigned int)((yy << 8) + xl);
                    while (win) {
                        int b = __ffs(win) - 1;
                        win &= win - 1;
                        int dx = b - u;
                        INS32(base + (unsigned int)b +
                              ((unsigned int)(dx * dx) << 16));
                    }
                }
            }
            done = true;   // provably exact: final d2_4 <= 53
        }
    }

    unsigned int ridx[4], rd2[4];

    if (!done) {
        // RESET: the failed fast-path seed may have left partial candidates in
        // k0..k3; the general loop rescans those rows at full width, and stale
        // entries would be re-inserted as duplicates. Start clean.
        k0 = k1 = k2 = k3 = ~0u;

        // ------- General path (borders / sparse seed): width-15 windows -------
        // Rows in increasing |dy|; width 15 until 4 held, then inclusive
        // floor(sqrt(B - dy^2)) (capped at 15). Every skipped cell has either
        // |dx| > 15 (d2 >= 256) or d2 > B >= final d2_4 -> exact iff final
        // d2_4 < 256. Max inserted d2 = 255^2 + 15^2 = 65250 < 2^16, so 32-bit
        // keys stay valid and below the ~0u sentinel.
        auto scan_row = [&](int yy, int lo, int hi) {
            if ((unsigned)yy >= SZ) return;
            lo = lo < 0 ? 0 : lo;
            hi = hi > SZ - 1 ? SZ - 1 : hi;
            const unsigned int* row = &m[yy << 3];
            const int wl = lo >> 5;
            // row[wl+1] may read the next row's word 0 (or the pad on the last
            // row); those bits are always masked out of the window.
            unsigned int win = __funnelshift_r(row[wl], row[wl + 1], lo);
            win &= 0xFFFFFFFFu >> (31 - (hi - lo));
            if (!win) return;
            const int dy = yy - y0;
            const unsigned int base =
                ((unsigned int)(dy * dy) << 16) + (unsigned int)((yy << 8) + lo);
            const int off = lo - x0;
            do {
                int b = __ffs(win) - 1;
                win &= win - 1;
                int dx = b + off;
                INS32(base + (unsigned int)b + ((unsigned int)(dx * dx) << 16));
            } while (win);
        };

        for (int dy = 0; dy < SZ; ++dy) {
            int u = 15;
            if (k3 != ~0u) {
                unsigned int B = k3 >> 16;
                unsigned int dy2 = (unsigned int)(dy * dy);
                if (dy2 > B) break;
                unsigned int rem = B - dy2;
                u = (rem >= 225u) ? 15 : (int)isq[rem];  // exact floor(sqrt)<=15
            }
            scan_row(y0 - dy, x0 - u, x0 + u);
            if (dy > 0) scan_row(y0 + dy, x0 - u, x0 + u);
        }

        if (!(k3 != ~0u && (k3 >> 16) < 256u)) {
            // ---- Essentially unreachable exact fallback: expanding rings ----
            unsigned long long b0 = ~0ULL, b1 = ~0ULL, b2 = ~0ULL, b3 = ~0ULL;
            int found = 0;
            auto visit = [&](int yy, int xx) {
                if ((unsigned)yy >= SZ || (unsigned)xx >= SZ) return;
                unsigned int word = m[(yy << 3) + (xx >> 5)];
                if ((word >> (xx & 31)) & 1u) {
                    int dy = yy - y0, dx = xx - x0;
                    unsigned int d2 = (unsigned int)(dy * dy + dx * dx);
                    unsigned long long key =
                        ((unsigned long long)d2 << 16) | (unsigned int)((yy << 8) + xx);
                    ++found;
                    if (key < b3) {
                        b3 = key;
                        if (b3 < b2) {
                            unsigned long long t = b2; b2 = b3; b3 = t;
                            if (b2 < b1) {
                                t = b1; b1 = b2; b2 = t;
                                if (b1 < b0) { t = b0; b0 = b1; b1 = t; }
                            }
                        }
                    }
                }
            };
            for (int r = 1; r < SZ; ++r) {
                if (found >= 4 && (unsigned int)(r * r) > (unsigned int)(b3 >> 16)) break;
                int yt = y0 - r, yb = y0 + r;
                for (int xx = x0 - r; xx <= x0 + r; ++xx) { visit(yt, xx); visit(yb, xx); }
                int xl = x0 - r, xr = x0 + r;
                for (int yy = y0 - r + 1; yy <= y0 + r - 1; ++yy) { visit(yy, xl); visit(yy, xr); }
            }
            unsigned long long keys[4] = { b0, b1, b2, b3 };
            #pragma unroll
            for (int i = 0; i < 4; ++i) {
                ridx[i] = (unsigned int)(keys[i] & 0xFFFFu);
                rd2[i]  = (unsigned int)(keys[i] >> 16);
            }
            goto output;
        }
    }

    ridx[0] = k0 & 0xFFFFu; rd2[0] = k0 >> 16;
    ridx[1] = k1 & 0xFFFFu; rd2[1] = k1 >> 16;
    ridx[2] = k2 & 0xFFFFu; rd2[2] = k2 >> 16;
    ridx[3] = k3 & 0xFFFFu; rd2[3] = k3 >> 16;

output:
    // Weighted by distance (as in reference), in top_k order. sqlut[d2] is
    // computed with the identical expression -> bit-exact; d2 < 256 on every
    // gated path, runtime check only matters for the fallback.
    float num = 0.0f, den = 0.0f;
    #pragma unroll
    for (int i = 0; i < 4; ++i) {
        unsigned int d2 = rd2[i];
        float dist = (d2 < 256u) ? sqlut[d2]
                                 : sqrtf((float)d2) * (1.0f / 256.0f);
        num += __ldg(&img[ridx[i]]) * dist;
        den += dist;
    }
    out[c * NPIX + pix] = num / den;
}

__global__ __launch_bounds__(512, 4) void knn_fill_kernel(
    const float* __restrict__ img, float* __restrict__ out)
{
    const int c   = blockIdx.y;          // channel 0..7
    const int tid = threadIdx.x;         // 0..511
    const int x0  = tid & 255;           // col
    const int sub = tid >> 8;            // which of the 2 rows

    // Channel bitmask (8KB) + 4 pad words for the last-row speculative read
    // (pad bits are always masked out of the window, value irrelevant).
    __shared__ __align__(16) unsigned int m[SZ * WPR + 4];
    __shared__ unsigned char isq[256];   // floor(sqrt(r)), r in [0,255]
    __shared__ float sqlut[256];         // sqrtf(r)/256, r in [0,255]

    // PDL prologue: LUTs depend only on thread id -> compute BEFORE the grid
    // dependency resolves, overlapping with build_masks_kernel.
    if (tid >= 256) {
        int r = tid - 256;               // 0..255
        int u = __float2int_rd(sqrtf((float)r));
        if ((u + 1) * (u + 1) <= r) ++u;
        if (u * u > r) --u;
        isq[r] = (unsigned char)u;
        sqlut[r] = sqrtf((float)r) * (1.0f / 256.0f);
    }

    cudaGridDependencySynchronize();     // build_masks results now visible

    if (tid < 256) {
        const uint4* src = (const uint4*)&g_maskbits[c * SZ * WPR];
        uint4* dst = (uint4*)m;
        dst[tid]       = src[tid];
        dst[tid + 256] = src[tid + 256];
    }
    __syncthreads();

    // Two rows per block, processed by independent warps.
    process_pixel(m, isq, sqlut, img, out, c, blockIdx.x * 2 + sub, x0);
}

extern "C" void kernel_launch(void* const* d_in, const int* in_sizes, int n_in,
                              void* d_out, int out_size) {
    const float* coded  = (const float*)d_in[0];   // [1,1,256,256]
    const int*   lookup = (const int*)d_in[1];     // [256,256]
    float* out = (float*)d_out;                    // [1,8,256,256]

    build_masks_kernel<<<SZ / 4, 1024>>>(lookup);

    // Programmatic dependent launch: overlap fill's launch + LUT prologue with
    // build_masks; correctness via cudaGridDependencySynchronize() in-kernel.
    cudaLaunchConfig_t cfg = {};
    cfg.gridDim  = dim3(SZ / 2, NCH);
    cfg.blockDim = dim3(512);
    cfg.stream   = 0;
    cudaLaunchAttribute attr[1];
    attr[0].id = cudaLaunchAttributeProgrammaticStreamSerialization;
    attr[0].val.programmaticStreamSerializationAllowed = 1;
    cfg.attrs = attr;
    cfg.numAttrs = 1;
    cudaLaunchKernelEx(&cfg, knn_fill_kernel, coded, out);
}